// round 12
// baseline (speedup 1.0000x reference)
#include <cuda_runtime.h>
#include <cuda_fp16.h>
#include <mma.h>

#define NNODES 100000
#define NP 100224               // padded node count (multiple of 128)
#define NEDGES 1600000
#define F0 128
#define F1 64
#define F2 16
#define NB1 ((NNODES + 255) / 256)   // 391 scan blocks

// Scratch (device globals: allocation-free, graph-safe)
__device__ float  g_dinv[NNODES];
__device__ __half g_h1h [NNODES * F1];   // H = x@W1 (UNSCALED), fp16 for gathers
__device__ float  g_t   [NNODES * F1];   // activated layer-1 output
__device__ float  g_h2  [NNODES * F2];   // h~2 = (t@W2)*dinv[row]
// dst-CSR scratch
__device__ int    g_hist  [NNODES];      // in-degree (dst)
__device__ int    g_rowptr[NNODES];
__device__ int    g_cursor[NNODES];
__device__ int    g_total;               // atomic range-claim counter
__device__ int    g_csr   [NEDGES];      // src ids grouped by dst

// ---------------------------------------------------------------------------
// Init: zero dst histogram + claim counter
// ---------------------------------------------------------------------------
__global__ void gcn_init_kernel() {
    int i = blockIdx.x * blockDim.x + threadIdx.x;
    if (i < NNODES) g_hist[i] = 0;
    if (i == 0) g_total = 0;
}

// ---------------------------------------------------------------------------
// In-degree histogram over dst (int4 = 4 edges/thread)
// ---------------------------------------------------------------------------
__global__ void gcn_hist_kernel(const int* __restrict__ dst) {
    int e4 = blockIdx.x * blockDim.x + threadIdx.x;
    if (e4 < NEDGES / 4) {
        int4 d = *(const int4*)&dst[e4 * 4];
        atomicAdd(&g_hist[d.x], 1);
        atomicAdd(&g_hist[d.y], 1);
        atomicAdd(&g_hist[d.z], 1);
        atomicAdd(&g_hist[d.w], 1);
    }
}

// ---------------------------------------------------------------------------
// scanclaim: per-block exclusive scan + UNORDERED atomic range claim.
// CSR ranges need only be disjoint and sized hist[v]; block order is
// irrelevant to the aggregation. Also computes dinv. (scan1+scan2+rowptr+dinv)
// ---------------------------------------------------------------------------
__global__ void gcn_scanclaim_kernel() {
    __shared__ int s[256];
    __shared__ int base;
    int tid = threadIdx.x;
    int i = blockIdx.x * 256 + tid;
    int v = (i < NNODES) ? g_hist[i] : 0;
    s[tid] = v;
    __syncthreads();
#pragma unroll
    for (int o = 1; o < 256; o <<= 1) {
        int t = (tid >= o) ? s[tid - o] : 0;
        __syncthreads();
        s[tid] += t;
        __syncthreads();
    }
    if (tid == 255) base = atomicAdd(&g_total, s[255]);
    __syncthreads();
    if (i < NNODES) {
        int p = base + s[tid] - v;   // exclusive within claimed range
        g_rowptr[i] = p;
        g_cursor[i] = p;
        g_dinv[i] = rsqrtf(1.0f + (float)v);
    }
}

// ---------------------------------------------------------------------------
// Permute: group src ids by dst (CSR fill), int4 = 4 edges/thread
// ---------------------------------------------------------------------------
__global__ void gcn_permute_kernel(const int* __restrict__ src,
                                   const int* __restrict__ dst) {
    int e4 = blockIdx.x * blockDim.x + threadIdx.x;
    if (e4 < NEDGES / 4) {
        int4 sv = *(const int4*)&src[e4 * 4];
        int4 dv = *(const int4*)&dst[e4 * 4];
        g_csr[atomicAdd(&g_cursor[dv.x], 1)] = sv.x;
        g_csr[atomicAdd(&g_cursor[dv.y], 1)] = sv.y;
        g_csr[atomicAdd(&g_cursor[dv.z], 1)] = sv.z;
        g_csr[atomicAdd(&g_cursor[dv.w], 1)] = sv.w;
    }
}

// ---------------------------------------------------------------------------
// GEMM1 via wmma (HMMA mma.sync — baseline PTX, works on compute_103):
//    g_h1h[v,:] = fp16( x[v,:] @ W1 )     -- UNSCALED; dinv applied in agg1.
// NO dependencies -> starts at t=0, overlaps the whole CSR-build chain.
// Per block: 128 rows x 64 cols x K=128. 256 threads = 8 warps.
// ---------------------------------------------------------------------------
#define A_LD 136               // halfs per A row (pad vs bank conflicts)
#define B_LD 72                // halfs per B row
#define D_LD 68                // floats per epilogue staging row
extern __shared__ __half s_wm[];

__global__ void gcn_gemm1_wmma(const float* __restrict__ x,
                               const float* __restrict__ W1) {
    using namespace nvcuda::wmma;
    __half* As = s_wm;                      // 128 * 136 halfs = 34816 B
    __half* Bs = s_wm + 128 * A_LD;         // 128 * 72 halfs  = 18432 B
    int tid = threadIdx.x, wid = tid >> 5;
    int row0 = blockIdx.x * 128;

    // Stage A: x rows -> fp16 (coalesced float4 loads, 8B STS)
    for (int i = tid; i < 128 * 32; i += 256) {
        int r = i >> 5, q = i & 31;
        int v = row0 + r;
        float4 xv = (v < NNODES) ? *(const float4*)&x[v * F0 + q * 4]
                                 : make_float4(0.f, 0.f, 0.f, 0.f);
        *(__half2*)&As[r * A_LD + q * 4]     = __floats2half2_rn(xv.x, xv.y);
        *(__half2*)&As[r * A_LD + q * 4 + 2] = __floats2half2_rn(xv.z, xv.w);
    }
    // Stage B: W1 [K=128][N=64] -> fp16
    for (int i = tid; i < 128 * 32; i += 256) {
        int k = i >> 5, n = (i & 31) * 2;
        float2 w = *(const float2*)&W1[k * F1 + n];
        *(__half2*)&Bs[k * B_LD + n] = __floats2half2_rn(w.x, w.y);
    }
    __syncthreads();

    fragment<accumulator, 16, 16, 16, float> acc[4];
#pragma unroll
    for (int c = 0; c < 4; c++) fill_fragment(acc[c], 0.0f);

    fragment<matrix_a, 16, 16, 16, __half, row_major> af;
    fragment<matrix_b, 16, 16, 16, __half, row_major> bf;
#pragma unroll
    for (int k = 0; k < 8; k++) {
        load_matrix_sync(af, As + wid * 16 * A_LD + k * 16, A_LD);
#pragma unroll
        for (int c = 0; c < 4; c++) {
            load_matrix_sync(bf, Bs + k * 16 * B_LD + c * 16, B_LD);
            mma_sync(acc[c], af, bf, acc[c]);
        }
    }

    // Epilogue: stage fp32 in smem (reuses As), convert to fp16, coalesced.
    __syncthreads();
    float* ds = (float*)s_wm;
#pragma unroll
    for (int c = 0; c < 4; c++)
        store_matrix_sync(&ds[(wid * 16) * D_LD + c * 16], acc[c],
                          D_LD, mem_row_major);
    __syncthreads();

    for (int i = tid; i < 128 * 32; i += 256) {
        int r = i >> 5, j = (i & 31) * 2;
        int v = row0 + r;
        if (v >= NNODES) continue;
        float2 u = *(const float2*)&ds[r * D_LD + j];
        *(__half2*)&g_h1h[v * F1 + j] = __floats2half2_rn(u.x, u.y);
    }
}

// ---------------------------------------------------------------------------
// Layer-1 aggregation + activation (warp per node, half2 per lane):
//    t[v] = leaky_relu(dinv[v] * (H[v]*dinv[v] + sum_s H[s]*dinv[s]) + b1)
// dinv[s] loads are warp-uniform (broadcast, 1 wavefront each, L2-resident).
// ---------------------------------------------------------------------------
__global__ void gcn_agg1_kernel(const float* __restrict__ b1) {
    int w = (blockIdx.x * blockDim.x + threadIdx.x) >> 5;
    int lane = threadIdx.x & 31;
    if (w >= NNODES) return;
    int v = w;
    int beg = g_rowptr[v];
    int len = g_hist[v];
    float dv = g_dinv[v];

    float2 hv = __half22float2(*(const __half2*)&g_h1h[v * F1 + lane * 2]);
    float2 acc = make_float2(hv.x * dv, hv.y * dv);   // self loop, scaled

    const int* __restrict__ idx = &g_csr[beg];
    int i = 0;
    for (; i + 4 <= len; i += 4) {
        int s0 = idx[i], s1 = idx[i + 1], s2 = idx[i + 2], s3 = idx[i + 3];
        float d0 = g_dinv[s0], d1 = g_dinv[s1], d2 = g_dinv[s2], d3 = g_dinv[s3];
        float2 u0 = __half22float2(*(const __half2*)&g_h1h[s0 * F1 + lane * 2]);
        float2 u1 = __half22float2(*(const __half2*)&g_h1h[s1 * F1 + lane * 2]);
        float2 u2 = __half22float2(*(const __half2*)&g_h1h[s2 * F1 + lane * 2]);
        float2 u3 = __half22float2(*(const __half2*)&g_h1h[s3 * F1 + lane * 2]);
        acc.x = fmaf(u0.x, d0, fmaf(u1.x, d1, fmaf(u2.x, d2, fmaf(u3.x, d3, acc.x))));
        acc.y = fmaf(u0.y, d0, fmaf(u1.y, d1, fmaf(u2.y, d2, fmaf(u3.y, d3, acc.y))));
    }
    for (; i < len; i++) {
        int s = idx[i];
        float d = g_dinv[s];
        float2 u = __half22float2(*(const __half2*)&g_h1h[s * F1 + lane * 2]);
        acc.x = fmaf(u.x, d, acc.x);
        acc.y = fmaf(u.y, d, acc.y);
    }

    float t0 = dv * acc.x + b1[lane * 2];
    float t1 = dv * acc.y + b1[lane * 2 + 1];
    t0 = t0 >= 0.f ? t0 : 0.2f * t0;
    t1 = t1 >= 0.f ? t1 : 0.2f * t1;
    *(float2*)&g_t[v * F1 + lane * 2] = make_float2(t0, t1);
}

// ---------------------------------------------------------------------------
// GEMM2: h2[v,:] = (t[v,:] @ W2) * dinv[v]    [N,64]x[64,16]
// ---------------------------------------------------------------------------
__global__ void gcn_gemm2_kernel(const float* __restrict__ W2) {
    __shared__ __align__(16) float W2s[F1 * F2];
    __shared__ __align__(16) float ts[16][F1];
    int tid = threadIdx.x;
    for (int i = tid; i < F1 * F2; i += 256) W2s[i] = W2[i];

    int v0 = blockIdx.x * 16;
    for (int i = tid; i < 16 * 16; i += 256) {
        int r = i >> 4, q = i & 15;
        *(float4*)&ts[r][q * 4] = *(const float4*)&g_t[(v0 + r) * F1 + q * 4];
    }
    __syncthreads();

    int r = tid >> 4;
    int m = tid & 15;
    int v = v0 + r;
    float acc = 0.f;
#pragma unroll
    for (int j = 0; j < F1; j++) acc += ts[r][j] * W2s[j * F2 + m];
    g_h2[v * F2 + m] = acc * g_dinv[v];
}

// ---------------------------------------------------------------------------
// Layer-2 aggregation + log_softmax (warp per node)
// ---------------------------------------------------------------------------
__global__ void gcn_agg2_kernel(const float* __restrict__ b2,
                                float* __restrict__ out) {
    int w = (blockIdx.x * blockDim.x + threadIdx.x) >> 5;
    int lane = threadIdx.x & 31;
    if (w >= NNODES) return;
    int v = w;
    int beg = g_rowptr[v];
    int len = g_hist[v];
    int f = lane & 15;

    float acc = 0.f;
    const int* __restrict__ idx = &g_csr[beg];
    for (int i = (lane >> 4); i < len; i += 2) {
        int s = idx[i];
        acc += g_h2[s * F2 + f];
    }
    acc += __shfl_down_sync(0xffffffffu, acc, 16);

    float dv = g_dinv[v];
    float t = dv * (acc + g_h2[v * F2 + f]) + b2[f];

    float mx = t;
#pragma unroll
    for (int o = 8; o >= 1; o >>= 1)
        mx = fmaxf(mx, __shfl_xor_sync(0xffffffffu, mx, o));
    float ex = expf(t - mx);
    float sum = ex;
#pragma unroll
    for (int o = 8; o >= 1; o >>= 1)
        sum += __shfl_xor_sync(0xffffffffu, sum, o);
    float lse = mx + logf(sum);

    if (lane < 16) out[v * F2 + f] = t - lse;
}

// ---------------------------------------------------------------------------
// Launch: fork-join graph (8 nodes).
//   sA: gemm1_wmma (t=0, NO deps) -> evS
//   s0: init -> hist -> scanclaim -> permute -> (wait evS) agg1 -> gemm2 -> agg2
// ---------------------------------------------------------------------------
extern "C" void kernel_launch(void* const* d_in, const int* in_sizes, int n_in,
                              void* d_out, int out_size) {
    const float* x  = (const float*)d_in[0];
    const int*   ei = (const int*)  d_in[1];
    const float* W1 = (const float*)d_in[2];
    const float* b1 = (const float*)d_in[3];
    const float* W2 = (const float*)d_in[4];
    const float* b2 = (const float*)d_in[5];
    float* out = (float*)d_out;

    const int* src = ei;
    const int* dst = ei + NEDGES;

    const int g1_smem = (128 * A_LD + 128 * B_LD) * (int)sizeof(__half); // 53.2KB
    cudaFuncSetAttribute(gcn_gemm1_wmma,
                         cudaFuncAttributeMaxDynamicSharedMemorySize, g1_smem);

    cudaStream_t sA;
    cudaStreamCreateWithFlags(&sA, cudaStreamNonBlocking);
    cudaEvent_t ev0, evS;
    cudaEventCreateWithFlags(&ev0, cudaEventDisableTiming);
    cudaEventCreateWithFlags(&evS, cudaEventDisableTiming);

    // fork: side stream joins capture via origin-stream event
    cudaEventRecord(ev0, 0);
    cudaStreamWaitEvent(sA, ev0, 0);

    gcn_gemm1_wmma<<<NP / 128, 256, g1_smem, sA>>>(x, W1);   // t=0, no deps
    cudaEventRecord(evS, sA);

    gcn_init_kernel     <<<(NNODES + 255) / 256, 256>>>();   // s0
    gcn_hist_kernel     <<<(NEDGES / 4 + 255) / 256, 256>>>(dst);
    gcn_scanclaim_kernel<<<NB1, 256>>>();
    gcn_permute_kernel  <<<(NEDGES / 4 + 255) / 256, 256>>>(src, dst);

    cudaStreamWaitEvent(0, evS, 0);                          // join
    gcn_agg1_kernel <<<(NNODES * 32 + 255) / 256, 256>>>(b1);
    gcn_gemm2_kernel<<<NNODES / 16, 256>>>(W2);
    gcn_agg2_kernel <<<(NNODES * 32 + 255) / 256, 256>>>(b2, out);
}

// round 13
// speedup vs baseline: 1.0316x; 1.0316x over previous
#include <cuda_runtime.h>
#include <cuda_fp16.h>
#include <mma.h>

#define NNODES 100000
#define NP 100224               // padded node count (multiple of 128)
#define NEDGES 1600000
#define F0 128
#define F1 64
#define F2 16
#define NB1 ((NNODES + 255) / 256)   // 391 scan blocks

// Scratch (device globals: allocation-free, graph-safe)
__device__ float  g_dinv[NNODES];
__device__ float  g_traw[NP * F1];       // gemm1 raw fp32 out (x@W1, unscaled)
__device__ __half g_h1h [NNODES * F1];   // h~ = (x@W1)*dinv[row], fp16 for gathers
__device__ float  g_h2  [NNODES * F2];   // h~2 = (t@W2)*dinv[row]
// dst-CSR scratch
__device__ int    g_hist  [NNODES];      // in-degree (dst)
__device__ int    g_rowptr[NNODES];
__device__ int    g_cursor[NNODES];
__device__ int    g_total;               // atomic range-claim counter
__device__ int    g_csr   [NEDGES];      // src ids grouped by dst

// ---------------------------------------------------------------------------
// Init: zero dst histogram + claim counter
// ---------------------------------------------------------------------------
__global__ void gcn_init_kernel() {
    int i = blockIdx.x * blockDim.x + threadIdx.x;
    if (i < NNODES) g_hist[i] = 0;
    if (i == 0) g_total = 0;
}

// ---------------------------------------------------------------------------
// In-degree histogram over dst (int4 = 4 edges/thread)
// ---------------------------------------------------------------------------
__global__ void gcn_hist_kernel(const int* __restrict__ dst) {
    int e4 = blockIdx.x * blockDim.x + threadIdx.x;
    if (e4 < NEDGES / 4) {
        int4 d = *(const int4*)&dst[e4 * 4];
        atomicAdd(&g_hist[d.x], 1);
        atomicAdd(&g_hist[d.y], 1);
        atomicAdd(&g_hist[d.z], 1);
        atomicAdd(&g_hist[d.w], 1);
    }
}

// ---------------------------------------------------------------------------
// scanclaim: per-block exclusive scan + UNORDERED atomic range claim.
// CSR ranges need only be disjoint and sized hist[v]; block order is
// irrelevant to the aggregation. Also computes dinv. (scan1+scan2+rowptr+dinv)
// ---------------------------------------------------------------------------
__global__ void gcn_scanclaim_kernel() {
    __shared__ int s[256];
    __shared__ int base;
    int tid = threadIdx.x;
    int i = blockIdx.x * 256 + tid;
    int v = (i < NNODES) ? g_hist[i] : 0;
    s[tid] = v;
    __syncthreads();
#pragma unroll
    for (int o = 1; o < 256; o <<= 1) {
        int t = (tid >= o) ? s[tid - o] : 0;
        __syncthreads();
        s[tid] += t;
        __syncthreads();
    }
    if (tid == 255) base = atomicAdd(&g_total, s[255]);
    __syncthreads();
    if (i < NNODES) {
        int p = base + s[tid] - v;   // exclusive within claimed range
        g_rowptr[i] = p;
        g_cursor[i] = p;
        g_dinv[i] = rsqrtf(1.0f + (float)v);
    }
}

// ---------------------------------------------------------------------------
// Permute: group src ids by dst (CSR fill), int4 = 4 edges/thread
// ---------------------------------------------------------------------------
__global__ void gcn_permute_kernel(const int* __restrict__ src,
                                   const int* __restrict__ dst) {
    int e4 = blockIdx.x * blockDim.x + threadIdx.x;
    if (e4 < NEDGES / 4) {
        int4 sv = *(const int4*)&src[e4 * 4];
        int4 dv = *(const int4*)&dst[e4 * 4];
        g_csr[atomicAdd(&g_cursor[dv.x], 1)] = sv.x;
        g_csr[atomicAdd(&g_cursor[dv.y], 1)] = sv.y;
        g_csr[atomicAdd(&g_cursor[dv.z], 1)] = sv.z;
        g_csr[atomicAdd(&g_cursor[dv.w], 1)] = sv.w;
    }
}

// ---------------------------------------------------------------------------
// GEMM1 via wmma (HMMA mma.sync — baseline PTX, works on compute_103):
//    g_traw[v,:] = x[v,:] @ W1   (fp16 in, fp32 accumulate, UNSCALED)
// NO dependencies -> starts at t=0, overlaps the whole CSR-build chain.
// Per block: 128 rows x 64 cols x K=128. 256 threads = 8 warps.
// ---------------------------------------------------------------------------
#define A_LD 136               // halfs per A row (pad vs bank conflicts)
#define B_LD 72                // halfs per B row
extern __shared__ __half s_wm[];

__global__ void gcn_gemm1_wmma(const float* __restrict__ x,
                               const float* __restrict__ W1) {
    using namespace nvcuda::wmma;
    __half* As = s_wm;                      // 128 * 136 halfs = 34816 B
    __half* Bs = s_wm + 128 * A_LD;         // 128 * 72 halfs  = 18432 B
    int tid = threadIdx.x, wid = tid >> 5;
    int row0 = blockIdx.x * 128;

    // Stage A: x rows -> fp16 (coalesced float4 loads, 8B STS)
    for (int i = tid; i < 128 * 32; i += 256) {
        int r = i >> 5, q = i & 31;
        int v = row0 + r;
        float4 xv = (v < NNODES) ? *(const float4*)&x[v * F0 + q * 4]
                                 : make_float4(0.f, 0.f, 0.f, 0.f);
        *(__half2*)&As[r * A_LD + q * 4]     = __floats2half2_rn(xv.x, xv.y);
        *(__half2*)&As[r * A_LD + q * 4 + 2] = __floats2half2_rn(xv.z, xv.w);
    }
    // Stage B: W1 [K=128][N=64] -> fp16
    for (int i = tid; i < 128 * 32; i += 256) {
        int k = i >> 5, n = (i & 31) * 2;
        float2 w = *(const float2*)&W1[k * F1 + n];
        *(__half2*)&Bs[k * B_LD + n] = __floats2half2_rn(w.x, w.y);
    }
    __syncthreads();

    fragment<accumulator, 16, 16, 16, float> acc[4];
#pragma unroll
    for (int c = 0; c < 4; c++) fill_fragment(acc[c], 0.0f);

    fragment<matrix_a, 16, 16, 16, __half, row_major> af;
    fragment<matrix_b, 16, 16, 16, __half, row_major> bf;
#pragma unroll
    for (int k = 0; k < 8; k++) {
        load_matrix_sync(af, As + wid * 16 * A_LD + k * 16, A_LD);
#pragma unroll
        for (int c = 0; c < 4; c++) {
            load_matrix_sync(bf, Bs + k * 16 * B_LD + c * 16, B_LD);
            mma_sync(acc[c], af, bf, acc[c]);
        }
    }

    // Store raw fp32 result (g_traw padded to NP rows; scaled later)
#pragma unroll
    for (int c = 0; c < 4; c++)
        store_matrix_sync(&g_traw[(row0 + wid * 16) * F1 + c * 16], acc[c],
                          F1, mem_row_major);
}

// ---------------------------------------------------------------------------
// scale_h1: g_h1h[v,:] = fp16( g_traw[v,:] * dinv[v] )
// ---------------------------------------------------------------------------
__global__ void gcn_scale_h1_kernel() {
    int t = blockIdx.x * blockDim.x + threadIdx.x;
    if (t >= NNODES * 32) return;
    int v = t >> 5, j = (t & 31) * 2;
    float dv = g_dinv[v];
    float2 u = *(const float2*)&g_traw[v * F1 + j];
    *(__half2*)&g_h1h[v * F1 + j] = __floats2half2_rn(u.x * dv, u.y * dv);
}

// ---------------------------------------------------------------------------
// FUSED layer-1 aggregation + activation + GEMM2:
//   warp per node: t = leaky_relu(dinv*(h1[v] + sum_s h1[s]) + b1)  -> smem
//   then 128 threads: h2[v,:] = (t @ W2) * dinv[v]
// Block = 256 threads = 8 warps = 8 nodes. Kills gemm2 kernel + g_t traffic.
// ---------------------------------------------------------------------------
__global__ void gcn_agg1_gemm2_kernel(const float* __restrict__ b1,
                                      const float* __restrict__ W2) {
    __shared__ __align__(16) float W2s[F1 * F2];   // 4 KB
    __shared__ __align__(16) float ts[8][F1 + 4];  // 8 nodes x 68
    __shared__ float b1s[F1];
    int tid = threadIdx.x, wid = tid >> 5, lane = tid & 31;
    int v = blockIdx.x * 8 + wid;

    for (int i = tid; i < F1 * F2; i += 256) W2s[i] = W2[i];
    if (tid < F1) b1s[tid] = b1[tid];
    __syncthreads();   // also guards ts reuse across launches (none)

    // --- agg1: warp per node, half2 per lane ---
    {
        int beg = g_rowptr[v];
        int len = g_hist[v];

        float2 acc = __half22float2(*(const __half2*)&g_h1h[v * F1 + lane * 2]);

        const int* __restrict__ idx = &g_csr[beg];
        int i = 0;
        for (; i + 4 <= len; i += 4) {
            int s0 = idx[i], s1 = idx[i + 1], s2 = idx[i + 2], s3 = idx[i + 3];
            float2 u0 = __half22float2(*(const __half2*)&g_h1h[s0 * F1 + lane * 2]);
            float2 u1 = __half22float2(*(const __half2*)&g_h1h[s1 * F1 + lane * 2]);
            float2 u2 = __half22float2(*(const __half2*)&g_h1h[s2 * F1 + lane * 2]);
            float2 u3 = __half22float2(*(const __half2*)&g_h1h[s3 * F1 + lane * 2]);
            acc.x += u0.x + u1.x + u2.x + u3.x;
            acc.y += u0.y + u1.y + u2.y + u3.y;
        }
        for (; i < len; i++) {
            int s = idx[i];
            float2 u = __half22float2(*(const __half2*)&g_h1h[s * F1 + lane * 2]);
            acc.x += u.x; acc.y += u.y;
        }

        float dv = g_dinv[v];
        float t0 = dv * acc.x + b1s[lane * 2];
        float t1 = dv * acc.y + b1s[lane * 2 + 1];
        t0 = t0 >= 0.f ? t0 : 0.2f * t0;
        t1 = t1 >= 0.f ? t1 : 0.2f * t1;
        *(float2*)&ts[wid][lane * 2] = make_float2(t0, t1);
    }
    __syncthreads();

    // --- gemm2: 128 threads, one (node r, feature m) each ---
    if (tid < 128) {
        int r = tid >> 4, m = tid & 15;
        int vr = blockIdx.x * 8 + r;
        float acc = 0.f;
#pragma unroll
        for (int j = 0; j < F1; j++) acc += ts[r][j] * W2s[j * F2 + m];
        g_h2[vr * F2 + m] = acc * g_dinv[vr];
    }
}

// ---------------------------------------------------------------------------
// Layer-2 aggregation + log_softmax (warp per node)
// ---------------------------------------------------------------------------
__global__ void gcn_agg2_kernel(const float* __restrict__ b2,
                                float* __restrict__ out) {
    int w = (blockIdx.x * blockDim.x + threadIdx.x) >> 5;
    int lane = threadIdx.x & 31;
    if (w >= NNODES) return;
    int v = w;
    int beg = g_rowptr[v];
    int len = g_hist[v];
    int f = lane & 15;

    float acc = 0.f;
    const int* __restrict__ idx = &g_csr[beg];
    for (int i = (lane >> 4); i < len; i += 2) {
        int s = idx[i];
        acc += g_h2[s * F2 + f];
    }
    acc += __shfl_down_sync(0xffffffffu, acc, 16);

    float dv = g_dinv[v];
    float t = dv * (acc + g_h2[v * F2 + f]) + b2[f];

    float mx = t;
#pragma unroll
    for (int o = 8; o >= 1; o >>= 1)
        mx = fmaxf(mx, __shfl_xor_sync(0xffffffffu, mx, o));
    float ex = expf(t - mx);
    float sum = ex;
#pragma unroll
    for (int o = 8; o >= 1; o >>= 1)
        sum += __shfl_xor_sync(0xffffffffu, sum, o);
    float lse = mx + logf(sum);

    if (lane < 16) out[v * F2 + f] = t - lse;
}

// ---------------------------------------------------------------------------
// Launch: fork-join graph (8 nodes).
//   sA: gemm1_wmma (t=0, NO deps) -> (wait evD) scale_h1 -> evS
//   s0: init -> hist -> scanclaim(evD) -> permute -> (wait evS) agg1gemm2 -> agg2
// ---------------------------------------------------------------------------
extern "C" void kernel_launch(void* const* d_in, const int* in_sizes, int n_in,
                              void* d_out, int out_size) {
    const float* x  = (const float*)d_in[0];
    const int*   ei = (const int*)  d_in[1];
    const float* W1 = (const float*)d_in[2];
    const float* b1 = (const float*)d_in[3];
    const float* W2 = (const float*)d_in[4];
    const float* b2 = (const float*)d_in[5];
    float* out = (float*)d_out;

    const int* src = ei;
    const int* dst = ei + NEDGES;

    const int g1_smem = (128 * A_LD + 128 * B_LD) * (int)sizeof(__half); // 53.2KB
    cudaFuncSetAttribute(gcn_gemm1_wmma,
                         cudaFuncAttributeMaxDynamicSharedMemorySize, g1_smem);

    cudaStream_t sA;
    cudaStreamCreateWithFlags(&sA, cudaStreamNonBlocking);
    cudaEvent_t ev0, evD, evS;
    cudaEventCreateWithFlags(&ev0, cudaEventDisableTiming);
    cudaEventCreateWithFlags(&evD, cudaEventDisableTiming);
    cudaEventCreateWithFlags(&evS, cudaEventDisableTiming);

    // fork: side stream joins capture via origin-stream event
    cudaEventRecord(ev0, 0);
    cudaStreamWaitEvent(sA, ev0, 0);

    gcn_gemm1_wmma<<<NP / 128, 256, g1_smem, sA>>>(x, W1);   // t=0, no deps

    gcn_init_kernel     <<<(NNODES + 255) / 256, 256>>>();   // s0
    gcn_hist_kernel     <<<(NEDGES / 4 + 255) / 256, 256>>>(dst);
    gcn_scanclaim_kernel<<<NB1, 256>>>();
    cudaEventRecord(evD, 0);

    cudaStreamWaitEvent(sA, evD, 0);                         // scale needs dinv
    gcn_scale_h1_kernel<<<(NNODES * 32 + 255) / 256, 256, 0, sA>>>();
    cudaEventRecord(evS, sA);

    gcn_permute_kernel<<<(NEDGES / 4 + 255) / 256, 256>>>(src, dst);  // overlaps

    cudaStreamWaitEvent(0, evS, 0);                          // join
    gcn_agg1_gemm2_kernel<<<NNODES / 8, 256>>>(b1, W2);
    gcn_agg2_kernel      <<<(NNODES * 32 + 255) / 256, 256>>>(b2, out);
}

// round 14
// speedup vs baseline: 1.0945x; 1.0610x over previous
#include <cuda_runtime.h>
#include <cuda_fp16.h>
#include <mma.h>

#define NNODES 100000
#define NP 100224               // padded node count (multiple of 64)
#define NEDGES 1600000
#define F0 128
#define F1 64
#define F2 16
#define NB1 ((NNODES + 255) / 256)   // 391 scan blocks

// Scratch (device globals: allocation-free, graph-safe)
__device__ float  g_dinv[NNODES];
__device__ float  g_traw[NP * F1];       // gemm1 raw fp32 out (x@W1, unscaled)
__device__ __half g_h1h [NNODES * F1];   // h~ = (x@W1)*dinv[row], fp16 for gathers
__device__ float  g_t   [NNODES * F1];   // activated layer-1 output
__device__ float  g_h2  [NNODES * F2];   // h~2 = (t@W2)*dinv[row]
// dst-CSR scratch
__device__ int    g_hist  [NNODES];      // in-degree (dst)
__device__ int    g_rowptr[NNODES];
__device__ int    g_cursor[NNODES];
__device__ int    g_total;               // atomic range-claim counter
__device__ int    g_csr   [NEDGES];      // src ids grouped by dst

// ---------------------------------------------------------------------------
// Init: zero dst histogram + claim counter
// ---------------------------------------------------------------------------
__global__ void gcn_init_kernel() {
    int i = blockIdx.x * blockDim.x + threadIdx.x;
    if (i < NNODES) g_hist[i] = 0;
    if (i == 0) g_total = 0;
}

// ---------------------------------------------------------------------------
// In-degree histogram over dst (int4 = 4 edges/thread)
// ---------------------------------------------------------------------------
__global__ void gcn_hist_kernel(const int* __restrict__ dst) {
    int e4 = blockIdx.x * blockDim.x + threadIdx.x;
    if (e4 < NEDGES / 4) {
        int4 d = *(const int4*)&dst[e4 * 4];
        atomicAdd(&g_hist[d.x], 1);
        atomicAdd(&g_hist[d.y], 1);
        atomicAdd(&g_hist[d.z], 1);
        atomicAdd(&g_hist[d.w], 1);
    }
}

// ---------------------------------------------------------------------------
// scanclaim: per-block exclusive scan + UNORDERED atomic range claim.
// CSR ranges need only be disjoint and sized hist[v]; block order is
// irrelevant to the aggregation. Also computes dinv. (scan1+scan2+rowptr+dinv)
// ---------------------------------------------------------------------------
__global__ void gcn_scanclaim_kernel() {
    __shared__ int s[256];
    __shared__ int base;
    int tid = threadIdx.x;
    int i = blockIdx.x * 256 + tid;
    int v = (i < NNODES) ? g_hist[i] : 0;
    s[tid] = v;
    __syncthreads();
#pragma unroll
    for (int o = 1; o < 256; o <<= 1) {
        int t = (tid >= o) ? s[tid - o] : 0;
        __syncthreads();
        s[tid] += t;
        __syncthreads();
    }
    if (tid == 255) base = atomicAdd(&g_total, s[255]);
    __syncthreads();
    if (i < NNODES) {
        int p = base + s[tid] - v;   // exclusive within claimed range
        g_rowptr[i] = p;
        g_cursor[i] = p;
        g_dinv[i] = rsqrtf(1.0f + (float)v);
    }
}

// ---------------------------------------------------------------------------
// Permute: group src ids by dst (CSR fill), int4 = 4 edges/thread
// ---------------------------------------------------------------------------
__global__ void gcn_permute_kernel(const int* __restrict__ src,
                                   const int* __restrict__ dst) {
    int e4 = blockIdx.x * blockDim.x + threadIdx.x;
    if (e4 < NEDGES / 4) {
        int4 sv = *(const int4*)&src[e4 * 4];
        int4 dv = *(const int4*)&dst[e4 * 4];
        g_csr[atomicAdd(&g_cursor[dv.x], 1)] = sv.x;
        g_csr[atomicAdd(&g_cursor[dv.y], 1)] = sv.y;
        g_csr[atomicAdd(&g_cursor[dv.z], 1)] = sv.z;
        g_csr[atomicAdd(&g_cursor[dv.w], 1)] = sv.w;
    }
}

// ---------------------------------------------------------------------------
// GEMM1 via wmma (HMMA mma.sync — baseline PTX, works on compute_103):
//    g_traw[v,:] = x[v,:] @ W1   (fp16 in, fp32 accumulate, UNSCALED)
// NO dependencies -> starts at t=0, overlaps the whole CSR-build chain.
// 64-row tiles: smem 35.8KB -> 4 blocks/SM (32 warps) for latency hiding.
// 256 threads = 8 warps: warp = (row-tile wid>>1, col-half wid&1),
// each warp: 2 col-tiles x 8 k-steps = 16 MMAs.
// ---------------------------------------------------------------------------
#define BM1 64
#define A_LD 136               // halfs per A row (pad vs bank conflicts)
#define B_LD 72                // halfs per B row
extern __shared__ __half s_wm[];

__global__ void gcn_gemm1_wmma(const float* __restrict__ x,
                               const float* __restrict__ W1) {
    using namespace nvcuda::wmma;
    __half* As = s_wm;                      // 64 * 136 halfs  = 17408 B
    __half* Bs = s_wm + BM1 * A_LD;         // 128 * 72 halfs  = 18432 B
    int tid = threadIdx.x, wid = tid >> 5;
    int row0 = blockIdx.x * BM1;

    // Stage A: x rows -> fp16 (coalesced float4 loads, 8B STS)
    for (int i = tid; i < BM1 * 32; i += 256) {
        int r = i >> 5, q = i & 31;
        int v = row0 + r;
        float4 xv = (v < NNODES) ? *(const float4*)&x[v * F0 + q * 4]
                                 : make_float4(0.f, 0.f, 0.f, 0.f);
        *(__half2*)&As[r * A_LD + q * 4]     = __floats2half2_rn(xv.x, xv.y);
        *(__half2*)&As[r * A_LD + q * 4 + 2] = __floats2half2_rn(xv.z, xv.w);
    }
    // Stage B: W1 [K=128][N=64] -> fp16
    for (int i = tid; i < 128 * 32; i += 256) {
        int k = i >> 5, n = (i & 31) * 2;
        float2 w = *(const float2*)&W1[k * F1 + n];
        *(__half2*)&Bs[k * B_LD + n] = __floats2half2_rn(w.x, w.y);
    }
    __syncthreads();

    int rt = wid >> 1;          // row tile 0..3 (16 rows each)
    int ch = wid & 1;           // column half 0..1 (32 cols each)

    fragment<accumulator, 16, 16, 16, float> acc[2];
#pragma unroll
    for (int c = 0; c < 2; c++) fill_fragment(acc[c], 0.0f);

    fragment<matrix_a, 16, 16, 16, __half, row_major> af;
    fragment<matrix_b, 16, 16, 16, __half, row_major> bf;
#pragma unroll
    for (int k = 0; k < 8; k++) {
        load_matrix_sync(af, As + rt * 16 * A_LD + k * 16, A_LD);
#pragma unroll
        for (int c = 0; c < 2; c++) {
            load_matrix_sync(bf, Bs + k * 16 * B_LD + ch * 32 + c * 16, B_LD);
            mma_sync(acc[c], af, bf, acc[c]);
        }
    }

    // Store raw fp32 result (g_traw padded to NP rows; scaled later)
#pragma unroll
    for (int c = 0; c < 2; c++)
        store_matrix_sync(&g_traw[(row0 + rt * 16) * F1 + ch * 32 + c * 16],
                          acc[c], F1, mem_row_major);
}

// ---------------------------------------------------------------------------
// scale_h1: g_h1h[v,:] = fp16( g_traw[v,:] * dinv[v] )
// ---------------------------------------------------------------------------
__global__ void gcn_scale_h1_kernel() {
    int t = blockIdx.x * blockDim.x + threadIdx.x;
    if (t >= NNODES * 32) return;
    int v = t >> 5, j = (t & 31) * 2;
    float dv = g_dinv[v];
    float2 u = *(const float2*)&g_traw[v * F1 + j];
    *(__half2*)&g_h1h[v * F1 + j] = __floats2half2_rn(u.x * dv, u.y * dv);
}

// ---------------------------------------------------------------------------
// Layer-1 aggregation + activation (warp per node, half2 per lane,
// warps fully independent — no block coupling):
//    t[v] = leaky_relu(dinv[v] * (h1[v] + sum_{s->v} h1[s]) + b1)
// ---------------------------------------------------------------------------
__global__ void gcn_agg1_kernel(const float* __restrict__ b1) {
    int w = (blockIdx.x * blockDim.x + threadIdx.x) >> 5;
    int lane = threadIdx.x & 31;
    if (w >= NNODES) return;
    int v = w;
    int beg = g_rowptr[v];
    int len = g_hist[v];

    float2 acc = __half22float2(*(const __half2*)&g_h1h[v * F1 + lane * 2]);

    const int* __restrict__ idx = &g_csr[beg];
    int i = 0;
    for (; i + 4 <= len; i += 4) {
        int s0 = idx[i], s1 = idx[i + 1], s2 = idx[i + 2], s3 = idx[i + 3];
        float2 u0 = __half22float2(*(const __half2*)&g_h1h[s0 * F1 + lane * 2]);
        float2 u1 = __half22float2(*(const __half2*)&g_h1h[s1 * F1 + lane * 2]);
        float2 u2 = __half22float2(*(const __half2*)&g_h1h[s2 * F1 + lane * 2]);
        float2 u3 = __half22float2(*(const __half2*)&g_h1h[s3 * F1 + lane * 2]);
        acc.x += u0.x + u1.x + u2.x + u3.x;
        acc.y += u0.y + u1.y + u2.y + u3.y;
    }
    for (; i < len; i++) {
        int s = idx[i];
        float2 u = __half22float2(*(const __half2*)&g_h1h[s * F1 + lane * 2]);
        acc.x += u.x; acc.y += u.y;
    }

    float dv = g_dinv[v];
    float t0 = dv * acc.x + b1[lane * 2];
    float t1 = dv * acc.y + b1[lane * 2 + 1];
    t0 = t0 >= 0.f ? t0 : 0.2f * t0;
    t1 = t1 >= 0.f ? t1 : 0.2f * t1;
    *(float2*)&g_t[v * F1 + lane * 2] = make_float2(t0, t1);
}

// ---------------------------------------------------------------------------
// GEMM2: h2[v,:] = (t[v,:] @ W2) * dinv[v]    [N,64]x[64,16]
// ---------------------------------------------------------------------------
__global__ void gcn_gemm2_kernel(const float* __restrict__ W2) {
    __shared__ __align__(16) float W2s[F1 * F2];
    __shared__ __align__(16) float ts[16][F1];
    int tid = threadIdx.x;
    for (int i = tid; i < F1 * F2; i += 256) W2s[i] = W2[i];

    int v0 = blockIdx.x * 16;
    for (int i = tid; i < 16 * 16; i += 256) {
        int r = i >> 4, q = i & 15;
        *(float4*)&ts[r][q * 4] = *(const float4*)&g_t[(v0 + r) * F1 + q * 4];
    }
    __syncthreads();

    int r = tid >> 4;
    int m = tid & 15;
    int v = v0 + r;
    float acc = 0.f;
#pragma unroll
    for (int j = 0; j < F1; j++) acc += ts[r][j] * W2s[j * F2 + m];
    g_h2[v * F2 + m] = acc * g_dinv[v];
}

// ---------------------------------------------------------------------------
// Layer-2 aggregation + log_softmax (warp per node)
// ---------------------------------------------------------------------------
__global__ void gcn_agg2_kernel(const float* __restrict__ b2,
                                float* __restrict__ out) {
    int w = (blockIdx.x * blockDim.x + threadIdx.x) >> 5;
    int lane = threadIdx.x & 31;
    if (w >= NNODES) return;
    int v = w;
    int beg = g_rowptr[v];
    int len = g_hist[v];
    int f = lane & 15;

    float acc = 0.f;
    const int* __restrict__ idx = &g_csr[beg];
    for (int i = (lane >> 4); i < len; i += 2) {
        int s = idx[i];
        acc += g_h2[s * F2 + f];
    }
    acc += __shfl_down_sync(0xffffffffu, acc, 16);

    float dv = g_dinv[v];
    float t = dv * (acc + g_h2[v * F2 + f]) + b2[f];

    float mx = t;
#pragma unroll
    for (int o = 8; o >= 1; o >>= 1)
        mx = fmaxf(mx, __shfl_xor_sync(0xffffffffu, mx, o));
    float ex = expf(t - mx);
    float sum = ex;
#pragma unroll
    for (int o = 8; o >= 1; o >>= 1)
        sum += __shfl_xor_sync(0xffffffffu, sum, o);
    float lse = mx + logf(sum);

    if (lane < 16) out[v * F2 + f] = t - lse;
}

// ---------------------------------------------------------------------------
// Launch: fork-join graph (9 nodes).
//   sA: gemm1_wmma (t=0, NO deps) -> (wait evD) scale_h1 -> evS
//   s0: init -> hist -> scanclaim(evD) -> permute -> (wait evS)
//       agg1 -> gemm2 -> agg2
// ---------------------------------------------------------------------------
extern "C" void kernel_launch(void* const* d_in, const int* in_sizes, int n_in,
                              void* d_out, int out_size) {
    const float* x  = (const float*)d_in[0];
    const int*   ei = (const int*)  d_in[1];
    const float* W1 = (const float*)d_in[2];
    const float* b1 = (const float*)d_in[3];
    const float* W2 = (const float*)d_in[4];
    const float* b2 = (const float*)d_in[5];
    float* out = (float*)d_out;

    const int* src = ei;
    const int* dst = ei + NEDGES;

    const int g1_smem = (BM1 * A_LD + 128 * B_LD) * (int)sizeof(__half); // 35.8KB
    cudaFuncSetAttribute(gcn_gemm1_wmma,
                         cudaFuncAttributeMaxDynamicSharedMemorySize, g1_smem);

    cudaStream_t sA;
    cudaStreamCreateWithFlags(&sA, cudaStreamNonBlocking);
    cudaEvent_t ev0, evD, evS;
    cudaEventCreateWithFlags(&ev0, cudaEventDisableTiming);
    cudaEventCreateWithFlags(&evD, cudaEventDisableTiming);
    cudaEventCreateWithFlags(&evS, cudaEventDisableTiming);

    // fork: side stream joins capture via origin-stream event
    cudaEventRecord(ev0, 0);
    cudaStreamWaitEvent(sA, ev0, 0);

    gcn_gemm1_wmma<<<NP / BM1, 256, g1_smem, sA>>>(x, W1);   // t=0, no deps

    gcn_init_kernel     <<<(NNODES + 255) / 256, 256>>>();   // s0
    gcn_hist_kernel     <<<(NEDGES / 4 + 255) / 256, 256>>>(dst);
    gcn_scanclaim_kernel<<<NB1, 256>>>();
    cudaEventRecord(evD, 0);

    cudaStreamWaitEvent(sA, evD, 0);                         // scale needs dinv
    gcn_scale_h1_kernel<<<(NNODES * 32 + 255) / 256, 256, 0, sA>>>();
    cudaEventRecord(evS, sA);

    gcn_permute_kernel<<<(NEDGES / 4 + 255) / 256, 256>>>(src, dst);  // overlaps

    cudaStreamWaitEvent(0, evS, 0);                          // join
    gcn_agg1_kernel <<<(NNODES * 32 + 255) / 256, 256>>>(b1);
    gcn_gemm2_kernel<<<NNODES / 16, 256>>>(W2);
    gcn_agg2_kernel <<<(NNODES * 32 + 255) / 256, 256>>>(b2, out);
}